// round 1
// baseline (speedup 1.0000x reference)
#include <cuda_runtime.h>
#include <cstdint>

// SpikeFP32ScaleBy2K: the soft-logic circuit is exactly
//   out = (k == ±0) ? x : x with exponent field replaced by
//         (e_x + kf) & 0xFF,  kf = sign(k) ? -|k| : |k| (int8),
//         |k| = (0x80 | top7(m_k)) >> (7 - ((e_k - 127) & 7))
// on IEEE-ish bit vectors stored as 0.0/1.0 floats (big-endian bit order).
//
// Layout: 8 lanes per row; each lane owns one float4 (4 bits) -> fully
// coalesced 16B accesses. Row words assembled via 3x shfl_xor OR-butterfly.

__global__ __launch_bounds__(256) void spike_scale_kernel(
    const uint4* __restrict__ x,
    const uint4* __restrict__ k,
    uint4* __restrict__ out,
    int n4)
{
    int t = blockIdx.x * blockDim.x + threadIdx.x;
    if (t >= n4) return;

    const unsigned seg = (unsigned)t & 7u;      // which float4 of the row (0..7)
    const unsigned sh  = 28u - 4u * seg;        // nibble position in packed word
                                                // (BE bit i -> uint bit 31-i)

    uint4 xu = x[t];
    uint4 ku = k[t];

    // Pack this lane's 4 bits (values are exactly 0.0f or 1.0f -> u==0 or u!=0)
    unsigned xn = (xu.x ? 8u : 0u) | (xu.y ? 4u : 0u) | (xu.z ? 2u : 0u) | (xu.w ? 1u : 0u);
    unsigned kn = (ku.x ? 8u : 0u) | (ku.y ? 4u : 0u) | (ku.z ? 2u : 0u) | (ku.w ? 1u : 0u);
    unsigned xw = xn << sh;
    unsigned kw = kn << sh;

    // OR-butterfly across the 8 lanes of this row (lanes are contiguous in warp)
    #pragma unroll
    for (int m = 1; m <= 4; m <<= 1) {
        xw |= __shfl_xor_sync(0xFFFFFFFFu, xw, m);
        kw |= __shfl_xor_sync(0xFFFFFFFFu, kw, m);
    }
    // Now xw/kw hold the full 32-bit words: sign@31, exp@30..23, mant@22..0.

    unsigned e_k  = (kw >> 23) & 0xFFu;
    unsigned s_k  = kw >> 31;
    unsigned kzero = ((kw & 0x7FFFFFFFu) == 0u);          // e_k==0 && m_k==0

    unsigned sh3  = (e_k - 127u) & 7u;                    // circuit uses low 3 bits only
    unsigned val  = 0x80u | ((kw >> 16) & 0x7Fu);         // {1, m_k[0:7]}
    unsigned kabs = val >> (7u - sh3);
    unsigned kf   = s_k ? ((0u - kabs) & 0xFFu) : kabs;   // two's complement if s_k

    unsigned e_x   = (xw >> 23) & 0xFFu;
    unsigned e_new = (e_x + kf) & 0xFFu;                  // 8-bit add, carry dropped

    unsigned ow = kzero ? xw : ((xw & 0x807FFFFFu) | (e_new << 23));

    // Unpack this lane's 4 output bits back to 0.0f / 1.0f
    unsigned b = ow >> sh;
    uint4 o;
    o.x = (b & 8u) ? 0x3F800000u : 0u;
    o.y = (b & 4u) ? 0x3F800000u : 0u;
    o.z = (b & 2u) ? 0x3F800000u : 0u;
    o.w = (b & 1u) ? 0x3F800000u : 0u;
    out[t] = o;
}

extern "C" void kernel_launch(void* const* d_in, const int* in_sizes, int n_in,
                              void* d_out, int out_size)
{
    const uint4* x = (const uint4*)d_in[0];
    const uint4* k = (const uint4*)d_in[1];
    uint4* o = (uint4*)d_out;

    int n4 = in_sizes[0] / 4;                 // number of float4s (= threads)
    int threads = 256;
    int blocks = (n4 + threads - 1) / threads;
    spike_scale_kernel<<<blocks, threads>>>(x, k, o, n4);
}